// round 15
// baseline (speedup 1.0000x reference)
#include <cuda_runtime.h>
#include <cuda_fp16.h>

#define NODES_MAX 50000
#define FEATS 128
#define KNBR 20
#define NTILES_MAX ((NODES_MAX + 127) / 128)

// fp16 planes, row-major [N][128]
__device__ __half g_Vh[NODES_MAX * FEATS];
__device__ __half g_Gh[NODES_MAX * FEATS];
__device__ int g_flag[NTILES_MAX];   // per-tile completed-node counters

// =================== helpers ===================
__device__ __forceinline__ unsigned int smem_u32(const void* p) {
    unsigned int a;
    asm("{ .reg .u64 t; cvta.to.shared.u64 t, %1; cvt.u32.u64 %0, t; }"
        : "=r"(a) : "l"(p));
    return a;
}
__device__ __forceinline__ void ldsm4(unsigned int r[4], unsigned int addr) {
    asm volatile("ldmatrix.sync.aligned.m8n8.x4.shared.b16 {%0,%1,%2,%3}, [%4];"
                 : "=r"(r[0]), "=r"(r[1]), "=r"(r[2]), "=r"(r[3])
                 : "r"(addr));
}
__device__ __forceinline__ void mma16816h(float c[4], const unsigned int a[4],
                                          unsigned int b0, unsigned int b1) {
    asm volatile(
        "mma.sync.aligned.m16n8k16.row.col.f32.f16.f16.f32 "
        "{%0,%1,%2,%3}, {%4,%5,%6,%7}, {%8,%9}, {%0,%1,%2,%3};"
        : "+f"(c[0]), "+f"(c[1]), "+f"(c[2]), "+f"(c[3])
        : "r"(a[0]), "r"(a[1]), "r"(a[2]), "r"(a[3]), "r"(b0), "r"(b1));
}
__device__ __forceinline__ void cp16(unsigned int dst, const void* src) {
    asm volatile("cp.async.cg.shared.global [%0], [%1], 16;"
                 :: "r"(dst), "l"(__cvta_generic_to_global(src)) : "memory");
}
#define CP_COMMIT() asm volatile("cp.async.commit_group;" ::: "memory")
#define CP_WAIT1()  asm volatile("cp.async.wait_group 1;" ::: "memory")
#define CP_WAIT0()  asm volatile("cp.async.wait_group 0;" ::: "memory")

__device__ __forceinline__ unsigned int sw128(unsigned int b) {
    return b ^ ((b >> 3) & 0x70);
}
// [128 x 128] fp16 K-major tile = two 64-k planes of 16KB, 128B rows
__device__ __forceinline__ unsigned int tile_off(int row, int k) {
    return ((unsigned)(k >> 6) << 14) + ((unsigned)row << 7) + ((unsigned)(k & 63) << 1);
}
__device__ __forceinline__ unsigned int pack2h(float a, float b) {
    __half2 p = __floats2half2_rn(a, b);
    return *reinterpret_cast<unsigned int*>(&p);
}

// ---------------- Kernel 0: V -> fp16 plane + zero flags ----------------
__global__ void conv_kernel(const float4* __restrict__ X4, int n4, int ntiles) {
    int i = blockIdx.x * blockDim.x + threadIdx.x;
    if (i < ntiles) g_flag[i] = 0;
    if (i < n4) {
        float4 v = X4[i];
        uint2 u = make_uint2(pack2h(v.x, v.y), pack2h(v.z, v.w));
        reinterpret_cast<uint2*>(g_Vh)[i] = u;
    }
}

// ---------------- Kernel 1: gather-aggregate + per-tile flag bump ----------------
__global__ void agg_kernel(const int* __restrict__ nh_idx,
                           const int* __restrict__ int_idx,
                           const float* __restrict__ nh_e,
                           const float* __restrict__ int_e,
                           int n) {
    int node = blockIdx.x * (blockDim.x >> 5) + (threadIdx.x >> 5);
    if (node >= n) return;
    int lane = threadIdx.x & 31;
    const uint2* Vb2 = reinterpret_cast<const uint2*>(g_Vh);

    int   iA = -1, iB = -1;
    float eA = 0.f, eB = 0.f;
    if (lane < KNBR) {
        int base = node * KNBR + lane;
        iA = nh_idx[base];
        eA = nh_e[base];
        iB = int_idx[base];
        eB = int_e[base];
    }
    int validB = __popc(__ballot_sync(0xffffffffu, (lane < KNBR) && (iB >= 0)));

    float4 acc = make_float4(0.f, 0.f, 0.f, 0.f);
#pragma unroll
    for (int j = 0; j < KNBR; j++) {
        int   idx = __shfl_sync(0xffffffffu, iA, j);
        float e   = __shfl_sync(0xffffffffu, eA, j);
        uint2 u   = __ldg(&Vb2[idx * 32 + lane]);
        float2 p0 = __half22float2(*reinterpret_cast<__half2*>(&u.x));
        float2 p1 = __half22float2(*reinterpret_cast<__half2*>(&u.y));
        acc.x = fmaf(e, p0.x, acc.x);
        acc.y = fmaf(e, p0.y, acc.y);
        acc.z = fmaf(e, p1.x, acc.z);
        acc.w = fmaf(e, p1.y, acc.w);
    }
#pragma unroll
    for (int j = 0; j < KNBR; j++) {
        int idx = __shfl_sync(0xffffffffu, iB, j);
        if (idx >= 0) {
            float e  = __shfl_sync(0xffffffffu, eB, j);
            uint2 u  = __ldg(&Vb2[idx * 32 + lane]);
            float2 p0 = __half22float2(*reinterpret_cast<__half2*>(&u.x));
            float2 p1 = __half22float2(*reinterpret_cast<__half2*>(&u.y));
            acc.x = fmaf(e, p0.x, acc.x);
            acc.y = fmaf(e, p0.y, acc.y);
            acc.z = fmaf(e, p1.x, acc.z);
            acc.w = fmaf(e, p1.y, acc.w);
        }
    }
    float inv = 1.0f / (float)(KNBR + validB);
    uint2 o = make_uint2(pack2h(acc.x * inv, acc.y * inv),
                         pack2h(acc.z * inv, acc.w * inv));
    reinterpret_cast<uint2*>(g_Gh)[node * 32 + lane] = o;

    if (lane == 0) {
        __threadfence();
        atomicAdd(&g_flag[node >> 7], 1);
    }
}

// =================== smem layout for gemm (dynamic) ===================
// [0]       weights: Wc (32KB), Wn (32KB) -- fp16 [n][k] K-major SW128
// [65536]   G chunk double buffer: 2 x 16KB
#define SM_B 0u
#define SM_A 65536u
#define SM_TOTAL 98304

// ---------------- Kernel 2: overlapped fp16 HMMA dual GEMM ----------------
// V-phase reads fp32 X directly (no dependency); G-phase waits per-tile flag.
__global__ __launch_bounds__(512, 1)
void gemm_tc(const float* __restrict__ X,
             const float* __restrict__ Wvc,
             const float* __restrict__ Wvn,
             const float* __restrict__ bv,
             float* __restrict__ out,
             int n, int ntiles) {
    extern __shared__ char smem[];
    unsigned int sb = smem_u32(smem);
    const int tid = threadIdx.x;
    const int wid = tid >> 5;
    const int lane = tid & 31;

    // ---- convert both weight matrices to smem fp16 planes ----
    for (int m = 0; m < 2; m++) {
        const float* W = m ? Wvn : Wvc;
        char* bp = smem + SM_B + m * 32768;
        for (int idx = tid; idx < 4096; idx += 512) {
            int k  = idx >> 5;
            int n4 = (idx & 31) << 2;
            float4 w = *reinterpret_cast<const float4*>(W + k * FEATS + n4);
            float wv[4] = {w.x, w.y, w.z, w.w};
#pragma unroll
            for (int i = 0; i < 4; i++) {
                unsigned int off = sw128(tile_off(n4 + i, k));
                *reinterpret_cast<__half*>(bp + off) = __float2half_rn(wv[i]);
            }
        }
    }
    __syncthreads();

    // G chunk loader: 16KB (one 64-k half) via cp.async
    auto load_chunk = [&](int buf, int tile, int h) {
        unsigned int dstBase = sb + SM_A + (unsigned)buf * 16384u;
        int idx = tid;
#pragma unroll
        for (int i = 0; i < 2; i++) {
            int row = idx >> 3;
            int u   = idx & 7;
            int gr = tile * 128 + row;
            if (gr >= n) gr = n - 1;
            unsigned int off = sw128((unsigned)(row * 128 + u * 16));
            cp16(dstBase + off, (const char*)g_Gh + (long long)gr * 256 + h * 128 + u * 16);
            idx += 512;
        }
    };

    // ---- per-warp addressing ----
    const int wm = wid & 3;        // 32-row block
    const int wn = wid >> 2;       // 32-col block
    const int mIdx = lane >> 3;
    const int r8 = lane & 7;

    const int rowA = wm * 32 + ((mIdx & 1) << 3) + r8;
    const unsigned int prowA =
        ((unsigned)rowA << 7) ^ (((unsigned)rowA & 7) << 4) ^ (((unsigned)mIdx >> 1) << 4);
    const int rowB = wn * 32 + ((mIdx >> 1) << 3) + r8;
    const unsigned int prowB =
        ((unsigned)rowB << 7) ^ (((unsigned)rowB & 7) << 4) ^ (((unsigned)mIdx & 1) << 4);

    float2 biasj[4];
#pragma unroll
    for (int j = 0; j < 4; j++) {
        int c = wn * 32 + j * 8 + ((lane & 3) << 1);
        biasj[j].x = __ldg(bv + c);
        biasj[j].y = __ldg(bv + c + 1);
    }

    for (int tile = blockIdx.x; tile < ntiles; tile += gridDim.x) {
        float acc[2][4][4];
#pragma unroll
        for (int i = 0; i < 2; i++)
#pragma unroll
            for (int j = 0; j < 4; j++)
#pragma unroll
                for (int q = 0; q < 4; q++) acc[i][j][q] = 0.f;

        // ======== V phase: A direct from fp32 X, B = Wc plane ========
        {
            const unsigned int WC = sb + SM_B;
            const int rbase = tile * 128 + wm * 32 + (lane >> 2);
#pragma unroll
            for (int ks = 0; ks < 8; ks++) {
                const unsigned int Kc =
                    (((unsigned)ks >> 2) << 14) | (((unsigned)ks & 3) << 5);
                unsigned int bh[2][4];
                ldsm4(bh[0], WC + (prowB ^ Kc));
                ldsm4(bh[1], WC + (prowB ^ 0x800u ^ Kc));

                const int kb = ks * 16 + ((lane & 3) << 1);
                unsigned int ah[2][4];
#pragma unroll
                for (int rb = 0; rb < 2; rb++) {
                    int r0 = rbase + rb * 16;
                    int r1 = r0 + 8;
                    if (r0 >= n) r0 = n - 1;
                    if (r1 >= n) r1 = n - 1;
                    const float* p0 = X + (long long)r0 * FEATS + kb;
                    const float* p1 = X + (long long)r1 * FEATS + kb;
                    float2 v00 = *reinterpret_cast<const float2*>(p0);
                    float2 v10 = *reinterpret_cast<const float2*>(p1);
                    float2 v01 = *reinterpret_cast<const float2*>(p0 + 8);
                    float2 v11 = *reinterpret_cast<const float2*>(p1 + 8);
                    ah[rb][0] = pack2h(v00.x, v00.y);
                    ah[rb][1] = pack2h(v10.x, v10.y);
                    ah[rb][2] = pack2h(v01.x, v01.y);
                    ah[rb][3] = pack2h(v11.x, v11.y);
                }
#pragma unroll
                for (int rb = 0; rb < 2; rb++) {
#pragma unroll
                    for (int cb = 0; cb < 4; cb++) {
                        unsigned int b0 = bh[cb >> 1][(cb & 1) * 2];
                        unsigned int b1 = bh[cb >> 1][(cb & 1) * 2 + 1];
                        mma16816h(acc[rb][cb], ah[rb], b0, b1);
                    }
                }
            }
        }

        // ======== wait for this tile's G rows ========
        if (tid == 0) {
            int expected = n - tile * 128;
            if (expected > 128) expected = 128;
            while (atomicAdd(&g_flag[tile], 0) < expected) __nanosleep(64);
            __threadfence();
        }
        __syncthreads();   // all threads done with prior tile's G bufs + flag seen

        // ======== G phase: both 64-k chunks, double buffered ========
        load_chunk(0, tile, 0);
        CP_COMMIT();
        load_chunk(1, tile, 1);
        CP_COMMIT();

        const unsigned int WN = sb + SM_B + 32768u;
        CP_WAIT1();
        __syncthreads();
#pragma unroll
        for (int half = 0; half < 2; half++) {
            const unsigned int aP = sb + SM_A + (unsigned)half * 16384u;
            const unsigned int bP = WN + (unsigned)half * 16384u;
#pragma unroll
            for (int ks = 0; ks < 4; ks++) {
                const unsigned int Kc = (unsigned)ks << 5;
                unsigned int ah[2][4], bh[2][4];
                ldsm4(ah[0], aP + (prowA ^ Kc));
                ldsm4(ah[1], aP + (prowA ^ 0x800u ^ Kc));
                ldsm4(bh[0], bP + (prowB ^ Kc));
                ldsm4(bh[1], bP + (prowB ^ 0x800u ^ Kc));
#pragma unroll
                for (int i = 0; i < 2; i++) {
#pragma unroll
                    for (int j = 0; j < 4; j++) {
                        unsigned int b0 = bh[j >> 1][(j & 1) * 2];
                        unsigned int b1 = bh[j >> 1][(j & 1) * 2 + 1];
                        mma16816h(acc[i][j], ah[i], b0, b1);
                    }
                }
            }
            if (half == 0) {
                CP_WAIT0();
                __syncthreads();
            }
        }

        // ---- epilogue: bias + relu + store ----
        int row_base = tile * 128 + wm * 32 + (lane >> 2);
#pragma unroll
        for (int i = 0; i < 2; i++) {
            int r0 = row_base + i * 16;
            int r1 = r0 + 8;
#pragma unroll
            for (int j = 0; j < 4; j++) {
                int col = wn * 32 + j * 8 + ((lane & 3) << 1);
                if (r0 < n) {
                    float2 o;
                    o.x = fmaxf(acc[i][j][0] + biasj[j].x, 0.f);
                    o.y = fmaxf(acc[i][j][1] + biasj[j].y, 0.f);
                    *reinterpret_cast<float2*>(out + (long long)r0 * FEATS + col) = o;
                }
                if (r1 < n) {
                    float2 o;
                    o.x = fmaxf(acc[i][j][2] + biasj[j].x, 0.f);
                    o.y = fmaxf(acc[i][j][3] + biasj[j].y, 0.f);
                    *reinterpret_cast<float2*>(out + (long long)r1 * FEATS + col) = o;
                }
            }
        }
    }
}

// ---------------- host side: capture-time stream fork ----------------
static cudaStream_t g_s2;
static cudaEvent_t g_e0, g_e1;
static bool g_ok = []() {
    if (cudaStreamCreateWithFlags(&g_s2, cudaStreamNonBlocking) != cudaSuccess) return false;
    if (cudaEventCreateWithFlags(&g_e0, cudaEventDisableTiming) != cudaSuccess) return false;
    if (cudaEventCreateWithFlags(&g_e1, cudaEventDisableTiming) != cudaSuccess) return false;
    return true;
}();

extern "C" void kernel_launch(void* const* d_in, const int* in_sizes, int n_in,
                              void* d_out, int out_size) {
    const float* vertices = (const float*)d_in[0];
    const int*   nh_idx   = (const int*)d_in[1];
    const int*   int_idx  = (const int*)d_in[2];
    const float* nh_e     = (const float*)d_in[3];
    const float* int_e    = (const float*)d_in[4];
    const float* Wvc      = (const float*)d_in[5];
    const float* Wvn      = (const float*)d_in[6];
    const float* bv       = (const float*)d_in[7];
    float* out = (float*)d_out;

    int n = in_sizes[0] / FEATS;  // 50000
    int ntiles = (n + 127) / 128;
    int n4 = n * 32;

    static bool attr_done = false;
    if (!attr_done) {
        cudaFuncSetAttribute(gemm_tc, cudaFuncAttributeMaxDynamicSharedMemorySize, SM_TOTAL);
        attr_done = true;
    }

    // conv (also zeroes flags) on main stream
    conv_kernel<<<(n4 + 255) / 256, 256>>>((const float4*)vertices, n4, ntiles);

    if (g_ok) {
        // fork: agg on s2 after conv; gemm on main concurrently
        cudaEventRecord(g_e0, 0);
        cudaStreamWaitEvent(g_s2, g_e0, 0);
        agg_kernel<<<(n + 7) / 8, 256, 0, g_s2>>>(nh_idx, int_idx, nh_e, int_e, n);
        cudaEventRecord(g_e1, g_s2);

        int grid = ntiles < 148 ? ntiles : 148;
        gemm_tc<<<grid, 512, SM_TOTAL>>>(vertices, Wvc, Wvn, bv, out, n, ntiles);

        cudaStreamWaitEvent(0, g_e1, 0);
    } else {
        // sequential fallback: flags are all set before gemm starts
        agg_kernel<<<(n + 7) / 8, 256>>>(nh_idx, int_idx, nh_e, int_e, n);
        int grid = ntiles < 148 ? ntiles : 148;
        gemm_tc<<<grid, 512, SM_TOTAL>>>(vertices, Wvc, Wvn, bv, out, n, ntiles);
    }
}